// round 16
// baseline (speedup 1.0000x reference)
#include <cuda_runtime.h>
#include <cuda_bf16.h>
#include <cstdint>

#define NN 50000
#define NE 800000
#define EPS_LN 1e-5f

// ---------------- scratch (no allocations allowed) ----------------
// g_agg, g_xhi/lo, g_ehi/lo are FRAGMENT-MAJOR per 64-col row:
//   uint32-slot q (bf16x2) / float-pair (2q,2q+1) holds logical cols
//   L = (q&7)*8 + (q>>3)*2  and L+1.
__device__ __align__(128) float g_agg[NN * 64];
__device__ __align__(128) float g_y[(size_t)NN * 128];
__device__ __align__(128) __nv_bfloat16 g_xhi[NN * 64], g_xlo[NN * 64];
__device__ __align__(128) __nv_bfloat16 g_ehi[(size_t)NE * 64], g_elo[(size_t)NE * 64];

// ---------------- helpers ----------------
__device__ __forceinline__ uint32_t smem_u32(const void* p) {
    uint32_t a;
    asm("{ .reg .u64 t; cvta.to.shared.u64 t, %1; cvt.u32.u64 %0, t; }" : "=r"(a) : "l"(p));
    return a;
}
__device__ __forceinline__ void split2(float f0, float f1, uint32_t& hi, uint32_t& lo) {
    uint32_t h;
    asm("cvt.rn.bf16x2.f32 %0, %1, %2;" : "=r"(h) : "f"(f1), "f"(f0));
    float h0 = __uint_as_float(h << 16);
    float h1 = __uint_as_float(h & 0xFFFF0000u);
    asm("cvt.rn.bf16x2.f32 %0, %1, %2;" : "=r"(lo) : "f"(f1 - h1), "f"(f0 - h0));
    hi = h;
}
__device__ __forceinline__ float2 join2(uint32_t hh, uint32_t ll) {
    float2 v;
    v.x = __uint_as_float(hh << 16) + __uint_as_float(ll << 16);
    v.y = __uint_as_float(hh & 0xFFFF0000u) + __uint_as_float(ll & 0xFFFF0000u);
    return v;
}
__device__ __forceinline__ void red4(float* p, float a, float b, float c, float d) {
    asm volatile("red.global.add.v4.f32 [%0], {%1, %2, %3, %4};"
                 :: "l"(p), "f"(a), "f"(b), "f"(c), "f"(d) : "memory");
}
__device__ __forceinline__ void ldm4(uint32_t r[4], uint32_t a) {
    asm volatile("ldmatrix.sync.aligned.m8n8.x4.shared.b16 {%0,%1,%2,%3}, [%4];"
                 : "=r"(r[0]), "=r"(r[1]), "=r"(r[2]), "=r"(r[3]) : "r"(a));
}
__device__ __forceinline__ void mma16816(float d[4], const uint32_t a[4],
                                         uint32_t b0, uint32_t b1) {
    asm volatile("mma.sync.aligned.m16n8k16.row.col.f32.bf16.bf16.f32 "
                 "{%0,%1,%2,%3},{%4,%5,%6,%7},{%8,%9},{%0,%1,%2,%3};"
                 : "+f"(d[0]), "+f"(d[1]), "+f"(d[2]), "+f"(d[3])
                 : "r"(a[0]), "r"(a[1]), "r"(a[2]), "r"(a[3]), "r"(b0), "r"(b1));
}
__device__ __forceinline__ void cpasync16(uint32_t dst, const void* src) {
    asm volatile("cp.async.ca.shared.global [%0], [%1], 16;" :: "r"(dst), "l"(src));
}
#define CP_COMMIT() asm volatile("cp.async.commit_group;" ::: "memory")
#define CP_WAIT0()  asm volatile("cp.async.wait_group 0;" ::: "memory")
#define CP_WAIT1()  asm volatile("cp.async.wait_group 1;" ::: "memory")

// fragment permutation: bf16 position kpos -> logical column
__device__ __forceinline__ int kperm(int kpos) {
    int q = kpos >> 1, b = kpos & 1;
    return (q & 7) * 8 + ((q >> 3) & 3) * 2 + b;
}

// ---- A from smem, TWO m16 tiles share B; caller initializes d ----
template <int KT>
__device__ __forceinline__ void layer_smemA2(float (&d)[2][8][4],
        const uint32_t (&aHi)[2], const uint32_t (&aLo)[2],
        uint32_t bHi, uint32_t bLo, int bstep) {
#pragma unroll
    for (int kt = 0; kt < KT; kt++) {
        uint32_t ah[2][4], al[2][4];
        ldm4(ah[0], aHi[0] + kt * 32); ldm4(al[0], aLo[0] + kt * 32);
        ldm4(ah[1], aHi[1] + kt * 32); ldm4(al[1], aLo[1] + kt * 32);
        uint32_t bh[4][4], bl[4][4];
#pragma unroll
        for (int np = 0; np < 4; np++) {
            ldm4(bh[np], bHi + np * bstep + kt * 32);
            ldm4(bl[np], bLo + np * bstep + kt * 32);
        }
#pragma unroll
        for (int np = 0; np < 4; np++)
#pragma unroll
            for (int t = 0; t < 2; t++) {
                mma16816(d[t][2 * np],     ah[t], bh[np][0], bh[np][1]);
                mma16816(d[t][2 * np + 1], ah[t], bh[np][2], bh[np][3]);
            }
#pragma unroll
        for (int np = 0; np < 4; np++)
#pragma unroll
            for (int t = 0; t < 2; t++) {
                mma16816(d[t][2 * np],     ah[t], bl[np][0], bl[np][1]);
                mma16816(d[t][2 * np + 1], ah[t], bl[np][2], bl[np][3]);
            }
#pragma unroll
        for (int np = 0; np < 4; np++)
#pragma unroll
            for (int t = 0; t < 2; t++) {
                mma16816(d[t][2 * np],     al[t], bh[np][0], bh[np][1]);
                mma16816(d[t][2 * np + 1], al[t], bh[np][2], bh[np][3]);
            }
    }
}

// ---- A in registers (K=64), two tiles share B ----
__device__ __forceinline__ void layer_regA2(float (&d)[2][8][4],
        const uint32_t (&aH)[2][4][4], const uint32_t (&aL)[2][4][4],
        uint32_t bHi, uint32_t bLo, int bstep) {
#pragma unroll
    for (int t = 0; t < 2; t++)
#pragma unroll
        for (int nt = 0; nt < 8; nt++)
            d[t][nt][0] = d[t][nt][1] = d[t][nt][2] = d[t][nt][3] = 0.f;
#pragma unroll
    for (int kt = 0; kt < 4; kt++) {
        uint32_t bh[4][4], bl[4][4];
#pragma unroll
        for (int np = 0; np < 4; np++) {
            ldm4(bh[np], bHi + np * bstep + kt * 32);
            ldm4(bl[np], bLo + np * bstep + kt * 32);
        }
#pragma unroll
        for (int np = 0; np < 4; np++)
#pragma unroll
            for (int t = 0; t < 2; t++) {
                mma16816(d[t][2 * np],     aH[t][kt], bh[np][0], bh[np][1]);
                mma16816(d[t][2 * np + 1], aH[t][kt], bh[np][2], bh[np][3]);
            }
#pragma unroll
        for (int np = 0; np < 4; np++)
#pragma unroll
            for (int t = 0; t < 2; t++) {
                mma16816(d[t][2 * np],     aH[t][kt], bl[np][0], bl[np][1]);
                mma16816(d[t][2 * np + 1], aH[t][kt], bl[np][2], bl[np][3]);
            }
#pragma unroll
        for (int np = 0; np < 4; np++)
#pragma unroll
            for (int t = 0; t < 2; t++) {
                mma16816(d[t][2 * np],     aL[t][kt], bh[np][0], bh[np][1]);
                mma16816(d[t][2 * np + 1], aL[t][kt], bh[np][2], bh[np][3]);
            }
    }
}

// accumulator fragments -> next-layer A fragments (standard order), in registers
__device__ __forceinline__ void inter_reg2(const float (&d)[2][8][4], const float* bias, int c,
                                           uint32_t (&aH)[2][4][4], uint32_t (&aL)[2][4][4]) {
#pragma unroll
    for (int t = 0; t < 2; t++)
#pragma unroll
        for (int kt = 0; kt < 4; kt++) {
            float2 b0 = *(const float2*)(bias + 16 * kt + 2 * c);
            split2(fmaxf(d[t][2 * kt][0] + b0.x, 0.f), fmaxf(d[t][2 * kt][1] + b0.y, 0.f),
                   aH[t][kt][0], aL[t][kt][0]);
            split2(fmaxf(d[t][2 * kt][2] + b0.x, 0.f), fmaxf(d[t][2 * kt][3] + b0.y, 0.f),
                   aH[t][kt][1], aL[t][kt][1]);
            float2 b1 = *(const float2*)(bias + 16 * kt + 8 + 2 * c);
            split2(fmaxf(d[t][2 * kt + 1][0] + b1.x, 0.f), fmaxf(d[t][2 * kt + 1][1] + b1.y, 0.f),
                   aH[t][kt][2], aL[t][kt][2]);
            split2(fmaxf(d[t][2 * kt + 1][2] + b1.x, 0.f), fmaxf(d[t][2 * kt + 1][3] + b1.y, 0.f),
                   aH[t][kt][3], aL[t][kt][3]);
        }
}

// stage W[k][n] as B[n][k] hi/lo, standard K order
__device__ __forceinline__ void stage_w(char* dsth, char* dstl, const float* W,
                                        int K, int bstr, int tid, int nthr) {
    for (int idx = tid; idx < K * 64; idx += nthr) {
        int k = idx >> 6, n = idx & 63;
        float f = W[idx];
        __nv_bfloat16 h = __float2bfloat16_rn(f);
        __nv_bfloat16 l = __float2bfloat16_rn(f - __bfloat162float(h));
        int off = n * bstr + k * 2;
        *(__nv_bfloat16*)(dsth + off) = h;
        *(__nv_bfloat16*)(dstl + off) = l;
    }
}
// stage with PERMUTED K (A operand is fragment-major): B[n][kpos] = W[kperm(kpos)][n]
__device__ __forceinline__ void stage_w_perm(char* dsth, char* dstl, const float* W,
                                             int bstr, int tid, int nthr) {
    for (int idx = tid; idx < 64 * 64; idx += nthr) {
        int kpos = idx >> 6, n = idx & 63;
        float f = W[kperm(kpos) * 64 + n];
        __nv_bfloat16 h = __float2bfloat16_rn(f);
        __nv_bfloat16 l = __float2bfloat16_rn(f - __bfloat162float(h));
        int off = n * bstr + kpos * 2;
        *(__nv_bfloat16*)(dsth + off) = h;
        *(__nv_bfloat16*)(dstl + off) = l;
    }
}

// ================= NODE-PARTIAL PRECOMPUTE (MMA) + agg zero =================
#define PRE_SMEM 110592

__global__ void __launch_bounds__(256, 1) node_pre_kernel(const float* __restrict__ W0) {
    extern __shared__ char sm[];
    const int tid = threadIdx.x, wid = tid >> 5, lane = tid & 31;
    const uint32_t smb = smem_u32(sm);

    for (int i = blockIdx.x * blockDim.x + tid; i < NN * 16; i += gridDim.x * blockDim.x)
        ((float4*)g_agg)[i] = make_float4(0.f, 0.f, 0.f, 0.f);

    // B = [W0 rows 0..63 | rows 64..127], K permuted (x is fragment-major)
    for (int idx = tid; idx < 128 * 64; idx += 256) {
        int j = idx >> 6, kpos = idx & 63;
        float f = W0[(kperm(kpos) + ((j >= 64) ? 64 : 0)) * 64 + (j & 63)];
        __nv_bfloat16 h = __float2bfloat16_rn(f);
        __nv_bfloat16 l = __float2bfloat16_rn(f - __bfloat162float(h));
        int off = j * 144 + kpos * 2;
        *(__nv_bfloat16*)(sm + 73728 + off) = h;
        *(__nv_bfloat16*)(sm + 92160 + off) = l;
    }
    __syncthreads();

    char* aHiP = sm + wid * 4608;
    char* aLoP = sm + 36864 + wid * 4608;
    const uint32_t aHiB = smb + wid * 4608, aLoB = smb + 36864 + wid * 4608;

    const int tq = lane >> 3;
    const int rA = (lane & 7) + ((tq & 1) << 3);
    const int kA = (tq >> 1) << 3;
    const uint32_t aHi[2] = { aHiB + rA * 144 + kA * 2, aHiB + (16 + rA) * 144 + kA * 2 };
    const uint32_t aLo[2] = { aLoB + rA * 144 + kA * 2, aLoB + (16 + rA) * 144 + kA * 2 };
    const int ofsB144 = ((tq >> 1) * 8 + (lane & 7)) * 144 + (tq & 1) * 16;
    const uint32_t bh = smb + 73728 + ofsB144, bl = smb + 92160 + ofsB144;

    const int g = lane >> 2, c = lane & 3;
    const int grr = lane >> 3, gcc = lane & 7;

    const int NWT = (NN + 31) / 32;
    for (int wt = blockIdx.x * 8 + wid; wt < NWT; wt += gridDim.x * 8) {
#pragma unroll
        for (int j = 0; j < 8; j++) {
            const int row = j * 4 + grr;
            const int n = wt * 32 + row;
            const int nc = (n < NN) ? n : (NN - 1);
            *(uint4*)(aHiP + row * 144 + gcc * 16) =
                *(const uint4*)((const char*)(g_xhi + (size_t)nc * 64) + gcc * 16);
            *(uint4*)(aLoP + row * 144 + gcc * 16) =
                *(const uint4*)((const char*)(g_xlo + (size_t)nc * 64) + gcc * 16);
        }
        __syncwarp();

#pragma unroll
        for (int half = 0; half < 2; half++) {
            float d[2][8][4];
#pragma unroll
            for (int t = 0; t < 2; t++)
#pragma unroll
                for (int nt = 0; nt < 8; nt++)
                    d[t][nt][0] = d[t][nt][1] = d[t][nt][2] = d[t][nt][3] = 0.f;
            layer_smemA2<4>(d, aHi, aLo, bh + half * 4 * 2304, bl + half * 4 * 2304, 2304);
#pragma unroll
            for (int t = 0; t < 2; t++) {
                const int n0 = wt * 32 + 16 * t + g, n1 = n0 + 8;
                const bool v0 = n0 < NN, v1 = n1 < NN;
                float2* o0 = (float2*)(g_y + (size_t)n0 * 128 + half * 64 + c * 16);
                float2* o1 = (float2*)(g_y + (size_t)n1 * 128 + half * 64 + c * 16);
#pragma unroll
                for (int nt = 0; nt < 8; nt++) {
                    if (v0) o0[nt] = make_float2(d[t][nt][0], d[t][nt][1]);
                    if (v1) o1[nt] = make_float2(d[t][nt][2], d[t][nt][3]);
                }
            }
        }
        __syncwarp();
    }
}

// ================= EDGE KERNEL =================
#define E_SMEM 204032

__global__ void __launch_bounds__(256, 1) edge_kernel(
    float* eout,
    const int* __restrict__ src, const int* __restrict__ dst,
    const float* __restrict__ W0, const float* __restrict__ b0,
    const float* __restrict__ W1, const float* __restrict__ b1,
    const float* __restrict__ W2, const float* __restrict__ b2,
    const float* __restrict__ gam, const float* __restrict__ bet, int fin)
{
    extern __shared__ char sm[];
    const int tid = threadIdx.x, wid = tid >> 5, lane = tid & 31;
    const uint32_t smb = smem_u32(sm);

    stage_w_perm(sm + 147456, sm + 156672, W0 + 128 * 64, 144, tid, 256);  // e-part, K perm
    stage_w(sm + 165888, sm + 175104, W1, 64, 144, tid, 256);
    stage_w(sm + 184320, sm + 193536, W2, 64, 144, tid, 256);
    float* fb = (float*)(sm + 202752);
    if (tid < 64) {
        fb[tid] = b0[tid]; fb[64 + tid] = b1[tid]; fb[128 + tid] = b2[tid];
        fb[192 + tid] = gam[tid]; fb[256 + tid] = bet[tid];
    }
    __syncthreads();

    const uint32_t aHiB[2] = { smb + wid * 4608, smb + 36864 + wid * 4608 };
    const uint32_t aLoB[2] = { smb + 73728 + wid * 4608, smb + 110592 + wid * 4608 };

    const int tq = lane >> 3;
    const int rA = (lane & 7) + ((tq & 1) << 3);
    const int kA = (tq >> 1) << 3;
    const int ofsB144 = ((tq >> 1) * 8 + (lane & 7)) * 144 + (tq & 1) * 16;
    const uint32_t b1h = smb + 147456 + ofsB144, b1l = smb + 156672 + ofsB144;
    const uint32_t b2h = smb + 165888 + ofsB144, b2l = smb + 175104 + ofsB144;
    const uint32_t b3h = smb + 184320 + ofsB144, b3l = smb + 193536 + ofsB144;

    const int g = lane >> 2, c = lane & 3;
    const int grr = lane >> 3, gcc = lane & 7;

    const int NWT = NE / 32;
    const int stride = gridDim.x * 8;
    int wt = blockIdx.x * 8 + wid;
    int buf = 0;

    if (wt < NWT) {
#pragma unroll
        for (int j = 0; j < 8; j++) {
            const int row = j * 4 + grr;
            const int ea = wt * 32 + row;
            cpasync16(aHiB[0] + row * 144 + gcc * 16,
                      (const char*)(g_ehi + (size_t)ea * 64) + gcc * 16);
            cpasync16(aLoB[0] + row * 144 + gcc * 16,
                      (const char*)(g_elo + (size_t)ea * 64) + gcc * 16);
        }
    }
    CP_COMMIT();

    for (; wt < NWT; wt += stride) {
        const int wtn = wt + stride;
        if (wtn < NWT) {
#pragma unroll
            for (int j = 0; j < 8; j++) {
                const int row = j * 4 + grr;
                const int ean = wtn * 32 + row;
                cpasync16(aHiB[buf ^ 1] + row * 144 + gcc * 16,
                          (const char*)(g_ehi + (size_t)ean * 64) + gcc * 16);
                cpasync16(aLoB[buf ^ 1] + row * 144 + gcc * 16,
                          (const char*)(g_elo + (size_t)ean * 64) + gcc * 16);
            }
            CP_COMMIT();
        }

        int sI[2][2], dI[2][2];
#pragma unroll
        for (int t = 0; t < 2; t++) {
            const int b = wt * 32 + 16 * t + g;
            sI[t][0] = __ldg(src + b); sI[t][1] = __ldg(src + b + 8);
            dI[t][0] = __ldg(dst + b); dI[t][1] = __ldg(dst + b + 8);
        }
        float d[2][8][4];
#pragma unroll
        for (int t = 0; t < 2; t++) {
            const float2* ys0 = (const float2*)(g_y + (size_t)sI[t][0] * 128 + c * 16);
            const float2* yd0 = (const float2*)(g_y + (size_t)dI[t][0] * 128 + 64 + c * 16);
            const float2* ys1 = (const float2*)(g_y + (size_t)sI[t][1] * 128 + c * 16);
            const float2* yd1 = (const float2*)(g_y + (size_t)dI[t][1] * 128 + 64 + c * 16);
#pragma unroll
            for (int nt = 0; nt < 8; nt++) {
                float2 a = ys0[nt], b = yd0[nt];
                d[t][nt][0] = a.x + b.x; d[t][nt][1] = a.y + b.y;
                a = ys1[nt]; b = yd1[nt];
                d[t][nt][2] = a.x + b.x; d[t][nt][3] = a.y + b.y;
            }
        }

        if (wtn < NWT) { CP_WAIT1(); } else { CP_WAIT0(); }
        __syncwarp();

        const uint32_t aHi[2] = { aHiB[buf] + rA * 144 + kA * 2,
                                  aHiB[buf] + (16 + rA) * 144 + kA * 2 };
        const uint32_t aLo[2] = { aLoB[buf] + rA * 144 + kA * 2,
                                  aLoB[buf] + (16 + rA) * 144 + kA * 2 };
        layer_smemA2<4>(d, aHi, aLo, b1h, b1l, 2304);

        uint32_t aH[2][4][4], aL[2][4][4];
        inter_reg2(d, fb, c, aH, aL);
        layer_regA2(d, aH, aL, b2h, b2l, 2304);
        inter_reg2(d, fb + 64, c, aH, aL);
        layer_regA2(d, aH, aL, b3h, b3l, 2304);

        char* aHiP = sm + (buf ? 36864 : 0) + wid * 4608;
        char* aLoP = sm + 73728 + (buf ? 36864 : 0) + wid * 4608;
        const float* b2v = fb + 128;
        const float* gmp = fb + 192;
        const float* btp = fb + 256;
#pragma unroll
        for (int t = 0; t < 2; t++) {
            const int r0 = 16 * t + g;
#pragma unroll
            for (int nt = 0; nt < 8; nt++) {
                int col = nt * 8 + 2 * c;
                float2 b = *(const float2*)(b2v + col);
                d[t][nt][0] += b.x; d[t][nt][1] += b.y;
                d[t][nt][2] += b.x; d[t][nt][3] += b.y;
            }
            float s0 = 0, q0 = 0, s1 = 0, q1 = 0;
#pragma unroll
            for (int nt = 0; nt < 8; nt++) {
                s0 += d[t][nt][0] + d[t][nt][1];
                q0 += d[t][nt][0] * d[t][nt][0] + d[t][nt][1] * d[t][nt][1];
                s1 += d[t][nt][2] + d[t][nt][3];
                q1 += d[t][nt][2] * d[t][nt][2] + d[t][nt][3] * d[t][nt][3];
            }
#pragma unroll
            for (int o = 1; o <= 2; o <<= 1) {
                s0 += __shfl_xor_sync(0xffffffffu, s0, o);
                q0 += __shfl_xor_sync(0xffffffffu, q0, o);
                s1 += __shfl_xor_sync(0xffffffffu, s1, o);
                q1 += __shfl_xor_sync(0xffffffffu, q1, o);
            }
            const float mu0 = s0 * (1.f / 64.f), mu1 = s1 * (1.f / 64.f);
            const float ri0 = rsqrtf(q0 * (1.f / 64.f) - mu0 * mu0 + EPS_LN);
            const float ri1 = rsqrtf(q1 * (1.f / 64.f) - mu1 * mu1 + EPS_LN);
            const int ea0 = wt * 32 + r0, ea1 = ea0 + 8;
            float* eo0 = eout + (size_t)ea0 * 64;
            float* eo1 = eout + (size_t)ea1 * 64;
            float* ag0 = g_agg + (size_t)dI[t][0] * 64 + c * 16;
            float* ag1 = g_agg + (size_t)dI[t][1] * 64 + c * 16;
#pragma unroll
            for (int ch = 0; ch < 2; ch++) {
                float a0v[8], a1v[8];
                uint32_t h0a[4], l0a[4], h1a[4], l1a[4];
#pragma unroll
                for (int k2 = 0; k2 < 4; k2++) {
                    const int nt = ch * 4 + k2;
                    const int col = nt * 8 + 2 * c;
                    const int so = (c * 8 + nt) * 4;   // fragment slot byte offset
                    float2 gmv = *(const float2*)(gmp + col);
                    float2 btv = *(const float2*)(btp + col);
                    float2 e0 = join2(*(const uint32_t*)(aHiP + r0 * 144 + so),
                                      *(const uint32_t*)(aLoP + r0 * 144 + so));
                    float2 e1 = join2(*(const uint32_t*)(aHiP + (r0 + 8) * 144 + so),
                                      *(const uint32_t*)(aLoP + (r0 + 8) * 144 + so));
                    float o0 = (d[t][nt][0] - mu0) * ri0 * gmv.x + btv.x + e0.x;
                    float o1 = (d[t][nt][1] - mu0) * ri0 * gmv.y + btv.y + e0.y;
                    float p0 = (d[t][nt][2] - mu1) * ri1 * gmv.x + btv.x + e1.x;
                    float p1 = (d[t][nt][3] - mu1) * ri1 * gmv.y + btv.y + e1.y;
                    a0v[k2 * 2] = o0; a0v[k2 * 2 + 1] = o1;
                    a1v[k2 * 2] = p0; a1v[k2 * 2 + 1] = p1;
                    if (fin) {
                        *(float2*)(eo0 + col) = make_float2(o0, o1);
                        *(float2*)(eo1 + col) = make_float2(p0, p1);
                    } else {
                        split2(o0, o1, h0a[k2], l0a[k2]);
                        split2(p0, p1, h1a[k2], l1a[k2]);
                    }
                }
                red4(ag0 + ch * 8,     a0v[0], a0v[1], a0v[2], a0v[3]);
                red4(ag0 + ch * 8 + 4, a0v[4], a0v[5], a0v[6], a0v[7]);
                red4(ag1 + ch * 8,     a1v[0], a1v[1], a1v[2], a1v[3]);
                red4(ag1 + ch * 8 + 4, a1v[4], a1v[5], a1v[6], a1v[7]);
                if (!fin) {
                    *(uint4*)((char*)g_ehi + (size_t)ea0 * 128 + c * 32 + ch * 16)
                        = make_uint4(h0a[0], h0a[1], h0a[2], h0a[3]);
                    *(uint4*)((char*)g_elo + (size_t)ea0 * 128 + c * 32 + ch * 16)
                        = make_uint4(l0a[0], l0a[1], l0a[2], l0a[3]);
                    *(uint4*)((char*)g_ehi + (size_t)ea1 * 128 + c * 32 + ch * 16)
                        = make_uint4(h1a[0], h1a[1], h1a[2], h1a[3]);
                    *(uint4*)((char*)g_elo + (size_t)ea1 * 128 + c * 32 + ch * 16)
                        = make_uint4(l1a[0], l1a[1], l1a[2], l1a[3]);
                }
            }
        }
        buf ^= 1;
    }
}

// ================= NODE KERNEL =================
#define N_SMEM 212224

__global__ void __launch_bounds__(256, 1) node_kernel(
    float* xout,
    const float* __restrict__ W0, const float* __restrict__ b0,
    const float* __restrict__ W1, const float* __restrict__ b1,
    const float* __restrict__ W2, const float* __restrict__ b2,
    const float* __restrict__ gam, const float* __restrict__ bet, int fin)
{
    extern __shared__ char sm[];
    const int tid = threadIdx.x, wid = tid >> 5, lane = tid & 31;
    const uint32_t smb = smem_u32(sm);

    // node B1: K=128 over [x | agg], BOTH halves fragment-major -> permute each half
    for (int idx = tid; idx < 128 * 64; idx += 256) {
        int kpos = idx >> 6, n = idx & 63;
        int base = (kpos >= 64) ? 64 : 0;
        float f = W0[(base + kperm(kpos & 63)) * 64 + n];
        __nv_bfloat16 h = __float2bfloat16_rn(f);
        __nv_bfloat16 l = __float2bfloat16_rn(f - __bfloat162float(h));
        int off = n * 272 + kpos * 2;
        *(__nv_bfloat16*)(sm + 139264 + off) = h;
        *(__nv_bfloat16*)(sm + 156672 + off) = l;
    }
    stage_w(sm + 174080, sm + 183296, W1, 64, 144, tid, 256);
    stage_w(sm + 192512, sm + 201728, W2, 64, 144, tid, 256);
    float* fb = (float*)(sm + 210944);
    if (tid < 64) {
        fb[tid] = b0[tid]; fb[64 + tid] = b1[tid]; fb[128 + tid] = b2[tid];
        fb[192 + tid] = gam[tid]; fb[256 + tid] = bet[tid];
    }
    __syncthreads();

    char* aHiP = sm + wid * 8704;
    char* aLoP = sm + 69632 + wid * 8704;
    const uint32_t aHiB = smb + wid * 8704, aLoB = smb + 69632 + wid * 8704;

    const int tq = lane >> 3;
    const int rA = (lane & 7) + ((tq & 1) << 3);
    const int kA = (tq >> 1) << 3;
    const uint32_t aHi[2] = { aHiB + rA * 272 + kA * 2, aHiB + (16 + rA) * 272 + kA * 2 };
    const uint32_t aLo[2] = { aLoB + rA * 272 + kA * 2, aLoB + (16 + rA) * 272 + kA * 2 };
    const int ofsB272 = ((tq >> 1) * 8 + (lane & 7)) * 272 + (tq & 1) * 16;
    const int ofsB144 = ((tq >> 1) * 8 + (lane & 7)) * 144 + (tq & 1) * 16;
    const uint32_t b1h = smb + 139264 + ofsB272, b1l = smb + 156672 + ofsB272;
    const uint32_t b2h = smb + 174080 + ofsB144, b2l = smb + 183296 + ofsB144;
    const uint32_t b3h = smb + 192512 + ofsB144, b3l = smb + 201728 + ofsB144;

    const int g = lane >> 2, c = lane & 3;
    const int grr = lane >> 3, gcc = lane & 7;
    const int arr = lane >> 4, acc_ = lane & 15;

    const int NWT = (NN + 31) / 32;
    for (int wt = blockIdx.x * 8 + wid; wt < NWT; wt += gridDim.x * 8) {
#pragma unroll
        for (int j = 0; j < 8; j++) {
            const int row = j * 4 + grr;
            const int n = wt * 32 + row;
            const int nc = (n < NN) ? n : (NN - 1);
            *(uint4*)(aHiP + row * 272 + gcc * 16) =
                *(const uint4*)((const char*)(g_xhi + (size_t)nc * 64) + gcc * 16);
            *(uint4*)(aLoP + row * 272 + gcc * 16) =
                *(const uint4*)((const char*)(g_xlo + (size_t)nc * 64) + gcc * 16);
        }
#pragma unroll
        for (int j = 0; j < 16; j++) {
            const int row = j * 2 + arr;
            const int n = wt * 32 + row;
            const int nc = (n < NN) ? n : (NN - 1);
            float4 v = *(const float4*)(g_agg + (size_t)nc * 64 + acc_ * 4);
            uint32_t h0, l0, h1, l1;
            split2(v.x, v.y, h0, l0);
            split2(v.z, v.w, h1, l1);
            *(uint2*)(aHiP + row * 272 + 128 + acc_ * 8) = make_uint2(h0, h1);
            *(uint2*)(aLoP + row * 272 + 128 + acc_ * 8) = make_uint2(l0, l1);
        }
        __syncwarp();

        float d[2][8][4];
#pragma unroll
        for (int t = 0; t < 2; t++)
#pragma unroll
            for (int nt = 0; nt < 8; nt++)
                d[t][nt][0] = d[t][nt][1] = d[t][nt][2] = d[t][nt][3] = 0.f;
        layer_smemA2<8>(d, aHi, aLo, b1h, b1l, 4352);
        uint32_t aH[2][4][4], aL[2][4][4];
        inter_reg2(d, fb, c, aH, aL);
        layer_regA2(d, aH, aL, b2h, b2l, 2304);
        inter_reg2(d, fb + 64, c, aH, aL);
        layer_regA2(d, aH, aL, b3h, b3l, 2304);

        const float* b2v = fb + 128;
        const float* gmp = fb + 192;
        const float* btp = fb + 256;
#pragma unroll
        for (int t = 0; t < 2; t++) {
            const int r0 = 16 * t + g;
#pragma unroll
            for (int nt = 0; nt < 8; nt++) {
                int col = nt * 8 + 2 * c;
                float2 b = *(const float2*)(b2v + col);
                d[t][nt][0] += b.x; d[t][nt][1] += b.y;
                d[t][nt][2] += b.x; d[t][nt][3] += b.y;
            }
            float s0 = 0, q0 = 0, s1 = 0, q1 = 0;
#pragma unroll
            for (int nt = 0; nt < 8; nt++) {
                s0 += d[t][nt][0] + d[t][nt][1];
                q0 += d[t][nt][0] * d[t][nt][0] + d[t][nt][1] * d[t][nt][1];
                s1 += d[t][nt][2] + d[t][nt][3];
                q1 += d[t][nt][2] * d[t][nt][2] + d[t][nt][3] * d[t][nt][3];
            }
#pragma unroll
            for (int o = 1; o <= 2; o <<= 1) {
                s0 += __shfl_xor_sync(0xffffffffu, s0, o);
                q0 += __shfl_xor_sync(0xffffffffu, q0, o);
                s1 += __shfl_xor_sync(0xffffffffu, s1, o);
                q1 += __shfl_xor_sync(0xffffffffu, q1, o);
            }
            const float mu0 = s0 * (1.f / 64.f), mu1 = s1 * (1.f / 64.f);
            const float ri0 = rsqrtf(q0 * (1.f / 64.f) - mu0 * mu0 + EPS_LN);
            const float ri1 = rsqrtf(q1 * (1.f / 64.f) - mu1 * mu1 + EPS_LN);
            const int n0 = wt * 32 + r0, n1 = n0 + 8;
            const bool v0 = n0 < NN, v1 = n1 < NN;
            float* xo0 = xout + (size_t)n0 * 64;
            float* xo1 = xout + (size_t)n1 * 64;
#pragma unroll
            for (int ch = 0; ch < 2; ch++) {
                uint32_t h0a[4], l0a[4], h1a[4], l1a[4];
#pragma unroll
                for (int k2 = 0; k2 < 4; k2++) {
                    const int nt = ch * 4 + k2;
                    const int col = nt * 8 + 2 * c;
                    const int so = (c * 8 + nt) * 4;
                    float2 gmv = *(const float2*)(gmp + col);
                    float2 btv = *(const float2*)(btp + col);
                    float2 x0 = join2(*(const uint32_t*)(aHiP + r0 * 272 + so),
                                      *(const uint32_t*)(aLoP + r0 * 272 + so));
                    float2 x1 = join2(*(const uint32_t*)(aHiP + (r0 + 8) * 272 + so),
                                      *(const uint32_t*)(aLoP + (r0 + 8) * 272 + so));
                    float o0 = (d[t][nt][0] - mu0) * ri0 * gmv.x + btv.x + x0.x;
                    float o1 = (d[t][nt][1] - mu0) * ri0 * gmv.y + btv.y + x0.y;
                    float p0 = (d[t][nt][2] - mu1) * ri1 * gmv.x + btv.x + x1.x;
                    float p1 = (d[t][nt][3] - mu1) * ri1 * gmv.y + btv.y + x1.y;
                    if (fin) {
                        if (v0) *(float2*)(xo0 + col) = make_float2(o0, o1);
                        if (v1) *(float2*)(xo1 + col) = make_float2(p0, p1);
                    } else {
                        split2(o0, o1, h0a[k2], l0a[k2]);
                        split2(p0, p1, h1a[k2], l1a[k2]);
                    }
                }
                if (!fin) {
                    if (v0) {
                        *(uint4*)((char*)g_xhi + (size_t)n0 * 128 + c * 32 + ch * 16)
                            = make_uint4(h0a[0], h0a[1], h0a[2], h0a[3]);
                        *(uint4*)((char*)g_xlo + (size_t)n0 * 128 + c * 32 + ch * 16)
                            = make_uint4(l0a[0], l0a[1], l0a[2], l0a[3]);
                    }
                    if (v1) {
                        *(uint4*)((char*)g_xhi + (size_t)n1 * 128 + c * 32 + ch * 16)
                            = make_uint4(h1a[0], h1a[1], h1a[2], h1a[3]);
                        *(uint4*)((char*)g_xlo + (size_t)n1 * 128 + c * 32 + ch * 16)
                            = make_uint4(l1a[0], l1a[1], l1a[2], l1a[3]);
                    }
                }
            }
        }
        __syncwarp();
    }
}

// ================= streaming split (fragment-major output) =================
__global__ void split_perm_kernel(const float* __restrict__ in,
                                  __nv_bfloat16* __restrict__ hi,
                                  __nv_bfloat16* __restrict__ lo, int nrows) {
    const int gw = (blockIdx.x * blockDim.x + threadIdx.x) >> 5;
    const int lane = threadIdx.x & 31;
    const int jq = (lane & 7) * 8 + (lane >> 3) * 2;   // logical col pair for slot=lane
    const int nwarps = gridDim.x * (blockDim.x >> 5);
    for (int row = gw; row < nrows; row += nwarps) {
        float2 v = *(const float2*)(in + (size_t)row * 64 + jq);
        uint32_t h, l;
        split2(v.x, v.y, h, l);
        ((uint32_t*)(hi + (size_t)row * 64))[lane] = h;
        ((uint32_t*)(lo + (size_t)row * 64))[lane] = l;
    }
}

// ================= launcher =================
extern "C" void kernel_launch(void* const* d_in, const int* in_sizes, int n_in,
                              void* d_out, int out_size) {
    const float* x_in = (const float*)d_in[0];
    const float* e_in = (const float*)d_in[1];
    const int* ei = (const int*)d_in[2];
    const int *src = ei, *dst = ei + NE;
    const float* ew0 = (const float*)d_in[3];  const float* eb0 = (const float*)d_in[4];
    const float* ew1 = (const float*)d_in[5];  const float* eb1 = (const float*)d_in[6];
    const float* ew2 = (const float*)d_in[7];  const float* eb2 = (const float*)d_in[8];
    const float* eg  = (const float*)d_in[9];  const float* ebt = (const float*)d_in[10];
    const float* nw0 = (const float*)d_in[11]; const float* nb0 = (const float*)d_in[12];
    const float* nw1 = (const float*)d_in[13]; const float* nb1 = (const float*)d_in[14];
    const float* nw2 = (const float*)d_in[15]; const float* nb2 = (const float*)d_in[16];
    const float* ng  = (const float*)d_in[17]; const float* nbt = (const float*)d_in[18];

    float* out_x = (float*)d_out;
    float* out_e = (float*)d_out + (size_t)NN * 64;

    __nv_bfloat16 *xhi, *xlo, *ehi, *elo;
    cudaGetSymbolAddress((void**)&xhi, g_xhi);
    cudaGetSymbolAddress((void**)&xlo, g_xlo);
    cudaGetSymbolAddress((void**)&ehi, g_ehi);
    cudaGetSymbolAddress((void**)&elo, g_elo);

    cudaFuncSetAttribute(edge_kernel, cudaFuncAttributeMaxDynamicSharedMemorySize, E_SMEM);
    cudaFuncSetAttribute(node_kernel, cudaFuncAttributeMaxDynamicSharedMemorySize, N_SMEM);
    cudaFuncSetAttribute(node_pre_kernel, cudaFuncAttributeMaxDynamicSharedMemorySize, PRE_SMEM);

    // keep edge_kernel at launch index 3 (ncu capture slot)
    split_perm_kernel<<<512, 256>>>(x_in, xhi, xlo, NN);            // 0
    split_perm_kernel<<<1024, 256>>>(e_in, ehi, elo, NE);           // 1

    const int EW0S = 192 * 64, EWS = 64 * 64, NW0S = 128 * 64;
    for (int i = 0; i < 3; i++) {
        const int fin = (i == 2) ? 1 : 0;
        node_pre_kernel<<<148, 256, PRE_SMEM>>>(ew0 + i * EW0S);    // 2, 5, 8
        edge_kernel<<<148, 256, E_SMEM>>>(                           // 3, 6, 9
            out_e, src, dst,
            ew0 + i * EW0S, eb0 + i * 64, ew1 + i * EWS, eb1 + i * 64,
            ew2 + i * EWS, eb2 + i * 64, eg + i * 64, ebt + i * 64, fin);
        node_kernel<<<148, 256, N_SMEM>>>(                           // 4, 7, 10
            out_x,
            nw0 + i * NW0S, nb0 + i * 64, nw1 + i * EWS, nb1 + i * 64,
            nw2 + i * EWS, nb2 + i * 64, ng + i * 64, nbt + i * 64, fin);
    }
}

// round 17
// speedup vs baseline: 1.0625x; 1.0625x over previous
#include <cuda_runtime.h>
#include <cuda_bf16.h>
#include <cstdint>

#define NN 50000
#define NE 800000
#define EPS_LN 1e-5f

// ---------------- scratch (no allocations allowed) ----------------
// g_agg, g_xhi/lo, g_ehi/lo are FRAGMENT-MAJOR per 64-col row:
//   uint32-slot q (bf16x2) / float-pair (2q,2q+1) holds logical cols
//   L = (q&7)*8 + (q>>3)*2  and L+1.
__device__ __align__(128) float g_agg[NN * 64];
__device__ __align__(128) float g_y[(size_t)NN * 128];
__device__ __align__(128) __nv_bfloat16 g_xhi[NN * 64], g_xlo[NN * 64];
__device__ __align__(128) __nv_bfloat16 g_ehi[(size_t)NE * 64], g_elo[(size_t)NE * 64];

// ---------------- helpers ----------------
__device__ __forceinline__ uint32_t smem_u32(const void* p) {
    uint32_t a;
    asm("{ .reg .u64 t; cvta.to.shared.u64 t, %1; cvt.u32.u64 %0, t; }" : "=r"(a) : "l"(p));
    return a;
}
__device__ __forceinline__ void split2(float f0, float f1, uint32_t& hi, uint32_t& lo) {
    uint32_t h;
    asm("cvt.rn.bf16x2.f32 %0, %1, %2;" : "=r"(h) : "f"(f1), "f"(f0));
    float h0 = __uint_as_float(h << 16);
    float h1 = __uint_as_float(h & 0xFFFF0000u);
    asm("cvt.rn.bf16x2.f32 %0, %1, %2;" : "=r"(lo) : "f"(f1 - h1), "f"(f0 - h0));
    hi = h;
}
__device__ __forceinline__ float2 join2(uint32_t hh, uint32_t ll) {
    float2 v;
    v.x = __uint_as_float(hh << 16) + __uint_as_float(ll << 16);
    v.y = __uint_as_float(hh & 0xFFFF0000u) + __uint_as_float(ll & 0xFFFF0000u);
    return v;
}
__device__ __forceinline__ void red4(float* p, float a, float b, float c, float d) {
    asm volatile("red.global.add.v4.f32 [%0], {%1, %2, %3, %4};"
                 :: "l"(p), "f"(a), "f"(b), "f"(c), "f"(d) : "memory");
}
__device__ __forceinline__ void ldm4(uint32_t r[4], uint32_t a) {
    asm volatile("ldmatrix.sync.aligned.m8n8.x4.shared.b16 {%0,%1,%2,%3}, [%4];"
                 : "=r"(r[0]), "=r"(r[1]), "=r"(r[2]), "=r"(r[3]) : "r"(a));
}
__device__ __forceinline__ void mma16816(float d[4], const uint32_t a[4],
                                         uint32_t b0, uint32_t b1) {
    asm volatile("mma.sync.aligned.m16n8k16.row.col.f32.bf16.bf16.f32 "
                 "{%0,%1,%2,%3},{%4,%5,%6,%7},{%8,%9},{%0,%1,%2,%3};"
                 : "+f"(d[0]), "+f"(d[1]), "+f"(d[2]), "+f"(d[3])
                 : "r"(a[0]), "r"(a[1]), "r"(a[2]), "r"(a[3]), "r"(b0), "r"(b1));
}
__device__ __forceinline__ void cpasync16(uint32_t dst, const void* src) {
    asm volatile("cp.async.ca.shared.global [%0], [%1], 16;" :: "r"(dst), "l"(src));
}
#define CP_COMMIT() asm volatile("cp.async.commit_group;" ::: "memory")
#define CP_WAIT0()  asm volatile("cp.async.wait_group 0;" ::: "memory")
#define CP_WAIT1()  asm volatile("cp.async.wait_group 1;" ::: "memory")

// fragment permutation: bf16 position kpos -> logical column
__device__ __forceinline__ int kperm(int kpos) {
    int q = kpos >> 1, b = kpos & 1;
    return (q & 7) * 8 + ((q >> 3) & 3) * 2 + b;
}

// ---- A from smem, TWO m16 tiles share B; caller initializes d ----
template <int KT>
__device__ __forceinline__ void layer_smemA2(float (&d)[2][8][4],
        const uint32_t (&aHi)[2], const uint32_t (&aLo)[2],
        uint32_t bHi, uint32_t bLo, int bstep) {
#pragma unroll
    for (int kt = 0; kt < KT; kt++) {
        uint32_t ah[2][4], al[2][4];
        ldm4(ah[0], aHi[0] + kt * 32); ldm4(al[0], aLo[0] + kt * 32);
        ldm4(ah[1], aHi[1] + kt * 32); ldm4(al[1], aLo[1] + kt * 32);
        uint32_t bh[4][4], bl[4][4];
#pragma unroll
        for (int np = 0; np < 4; np++) {
            ldm4(bh[np], bHi + np * bstep + kt * 32);
            ldm4(bl[np], bLo + np * bstep + kt * 32);
        }
#pragma unroll
        for (int np = 0; np < 4; np++)
#pragma unroll
            for (int t = 0; t < 2; t++) {
                mma16816(d[t][2 * np],     ah[t], bh[np][0], bh[np][1]);
                mma16816(d[t][2 * np + 1], ah[t], bh[np][2], bh[np][3]);
            }
#pragma unroll
        for (int np = 0; np < 4; np++)
#pragma unroll
            for (int t = 0; t < 2; t++) {
                mma16816(d[t][2 * np],     ah[t], bl[np][0], bl[np][1]);
                mma16816(d[t][2 * np + 1], ah[t], bl[np][2], bl[np][3]);
            }
#pragma unroll
        for (int np = 0; np < 4; np++)
#pragma unroll
            for (int t = 0; t < 2; t++) {
                mma16816(d[t][2 * np],     al[t], bh[np][0], bh[np][1]);
                mma16816(d[t][2 * np + 1], al[t], bh[np][2], bh[np][3]);
            }
    }
}

// ---- A in registers (K=64), two tiles share B ----
__device__ __forceinline__ void layer_regA2(float (&d)[2][8][4],
        const uint32_t (&aH)[2][4][4], const uint32_t (&aL)[2][4][4],
        uint32_t bHi, uint32_t bLo, int bstep) {
#pragma unroll
    for (int t = 0; t < 2; t++)
#pragma unroll
        for (int nt = 0; nt < 8; nt++)
            d[t][nt][0] = d[t][nt][1] = d[t][nt][2] = d[t][nt][3] = 0.f;
#pragma unroll
    for (int kt = 0; kt < 4; kt++) {
        uint32_t bh[4][4], bl[4][4];
#pragma unroll
        for (int np = 0; np < 4; np++) {
            ldm4(bh[np], bHi + np * bstep + kt * 32);
            ldm4(bl[np], bLo + np * bstep + kt * 32);
        }
#pragma unroll
        for (int np = 0; np < 4; np++)
#pragma unroll
            for (int t = 0; t < 2; t++) {
                mma16816(d[t][2 * np],     aH[t][kt], bh[np][0], bh[np][1]);
                mma16816(d[t][2 * np + 1], aH[t][kt], bh[np][2], bh[np][3]);
            }
#pragma unroll
        for (int np = 0; np < 4; np++)
#pragma unroll
            for (int t = 0; t < 2; t++) {
                mma16816(d[t][2 * np],     aH[t][kt], bl[np][0], bl[np][1]);
                mma16816(d[t][2 * np + 1], aH[t][kt], bl[np][2], bl[np][3]);
            }
#pragma unroll
        for (int np = 0; np < 4; np++)
#pragma unroll
            for (int t = 0; t < 2; t++) {
                mma16816(d[t][2 * np],     aL[t][kt], bh[np][0], bh[np][1]);
                mma16816(d[t][2 * np + 1], aL[t][kt], bh[np][2], bh[np][3]);
            }
    }
}

// accumulator fragments -> next-layer A fragments (standard order), in registers
__device__ __forceinline__ void inter_reg2(const float (&d)[2][8][4], const float* bias, int c,
                                           uint32_t (&aH)[2][4][4], uint32_t (&aL)[2][4][4]) {
#pragma unroll
    for (int t = 0; t < 2; t++)
#pragma unroll
        for (int kt = 0; kt < 4; kt++) {
            float2 b0 = *(const float2*)(bias + 16 * kt + 2 * c);
            split2(fmaxf(d[t][2 * kt][0] + b0.x, 0.f), fmaxf(d[t][2 * kt][1] + b0.y, 0.f),
                   aH[t][kt][0], aL[t][kt][0]);
            split2(fmaxf(d[t][2 * kt][2] + b0.x, 0.f), fmaxf(d[t][2 * kt][3] + b0.y, 0.f),
                   aH[t][kt][1], aL[t][kt][1]);
            float2 b1 = *(const float2*)(bias + 16 * kt + 8 + 2 * c);
            split2(fmaxf(d[t][2 * kt + 1][0] + b1.x, 0.f), fmaxf(d[t][2 * kt + 1][1] + b1.y, 0.f),
                   aH[t][kt][2], aL[t][kt][2]);
            split2(fmaxf(d[t][2 * kt + 1][2] + b1.x, 0.f), fmaxf(d[t][2 * kt + 1][3] + b1.y, 0.f),
                   aH[t][kt][3], aL[t][kt][3]);
        }
}

// stage W[k][n] as B[n][k] hi/lo, standard K order
__device__ __forceinline__ void stage_w(char* dsth, char* dstl, const float* W,
                                        int K, int bstr, int tid, int nthr) {
    for (int idx = tid; idx < K * 64; idx += nthr) {
        int k = idx >> 6, n = idx & 63;
        float f = W[idx];
        __nv_bfloat16 h = __float2bfloat16_rn(f);
        __nv_bfloat16 l = __float2bfloat16_rn(f - __bfloat162float(h));
        int off = n * bstr + k * 2;
        *(__nv_bfloat16*)(dsth + off) = h;
        *(__nv_bfloat16*)(dstl + off) = l;
    }
}
// stage with PERMUTED K (A operand is fragment-major): B[n][kpos] = W[kperm(kpos)][n]
__device__ __forceinline__ void stage_w_perm(char* dsth, char* dstl, const float* W,
                                             int bstr, int tid, int nthr) {
    for (int idx = tid; idx < 64 * 64; idx += nthr) {
        int kpos = idx >> 6, n = idx & 63;
        float f = W[kperm(kpos) * 64 + n];
        __nv_bfloat16 h = __float2bfloat16_rn(f);
        __nv_bfloat16 l = __float2bfloat16_rn(f - __bfloat162float(h));
        int off = n * bstr + kpos * 2;
        *(__nv_bfloat16*)(dsth + off) = h;
        *(__nv_bfloat16*)(dstl + off) = l;
    }
}

// ================= NODE-PARTIAL PRECOMPUTE (MMA) + agg zero =================
#define PRE_SMEM 110592

__global__ void __launch_bounds__(256, 1) node_pre_kernel(const float* __restrict__ W0) {
    extern __shared__ char sm[];
    const int tid = threadIdx.x, wid = tid >> 5, lane = tid & 31;
    const uint32_t smb = smem_u32(sm);

    for (int i = blockIdx.x * blockDim.x + tid; i < NN * 16; i += gridDim.x * blockDim.x)
        ((float4*)g_agg)[i] = make_float4(0.f, 0.f, 0.f, 0.f);

    // B = [W0 rows 0..63 | rows 64..127], K permuted (x is fragment-major)
    for (int idx = tid; idx < 128 * 64; idx += 256) {
        int j = idx >> 6, kpos = idx & 63;
        float f = W0[(kperm(kpos) + ((j >= 64) ? 64 : 0)) * 64 + (j & 63)];
        __nv_bfloat16 h = __float2bfloat16_rn(f);
        __nv_bfloat16 l = __float2bfloat16_rn(f - __bfloat162float(h));
        int off = j * 144 + kpos * 2;
        *(__nv_bfloat16*)(sm + 73728 + off) = h;
        *(__nv_bfloat16*)(sm + 92160 + off) = l;
    }
    __syncthreads();

    char* aHiP = sm + wid * 4608;
    char* aLoP = sm + 36864 + wid * 4608;
    const uint32_t aHiB = smb + wid * 4608, aLoB = smb + 36864 + wid * 4608;

    const int tq = lane >> 3;
    const int rA = (lane & 7) + ((tq & 1) << 3);
    const int kA = (tq >> 1) << 3;
    const uint32_t aHi[2] = { aHiB + rA * 144 + kA * 2, aHiB + (16 + rA) * 144 + kA * 2 };
    const uint32_t aLo[2] = { aLoB + rA * 144 + kA * 2, aLoB + (16 + rA) * 144 + kA * 2 };
    const int ofsB144 = ((tq >> 1) * 8 + (lane & 7)) * 144 + (tq & 1) * 16;
    const uint32_t bh = smb + 73728 + ofsB144, bl = smb + 92160 + ofsB144;

    const int g = lane >> 2, c = lane & 3;
    const int grr = lane >> 3, gcc = lane & 7;

    const int NWT = (NN + 31) / 32;
    for (int wt = blockIdx.x * 8 + wid; wt < NWT; wt += gridDim.x * 8) {
#pragma unroll
        for (int j = 0; j < 8; j++) {
            const int row = j * 4 + grr;
            const int n = wt * 32 + row;
            const int nc = (n < NN) ? n : (NN - 1);
            *(uint4*)(aHiP + row * 144 + gcc * 16) =
                *(const uint4*)((const char*)(g_xhi + (size_t)nc * 64) + gcc * 16);
            *(uint4*)(aLoP + row * 144 + gcc * 16) =
                *(const uint4*)((const char*)(g_xlo + (size_t)nc * 64) + gcc * 16);
        }
        __syncwarp();

#pragma unroll
        for (int half = 0; half < 2; half++) {
            float d[2][8][4];
#pragma unroll
            for (int t = 0; t < 2; t++)
#pragma unroll
                for (int nt = 0; nt < 8; nt++)
                    d[t][nt][0] = d[t][nt][1] = d[t][nt][2] = d[t][nt][3] = 0.f;
            layer_smemA2<4>(d, aHi, aLo, bh + half * 4 * 2304, bl + half * 4 * 2304, 2304);
#pragma unroll
            for (int t = 0; t < 2; t++) {
                const int n0 = wt * 32 + 16 * t + g, n1 = n0 + 8;
                const bool v0 = n0 < NN, v1 = n1 < NN;
                float4* o0 = (float4*)(g_y + (size_t)n0 * 128 + half * 64 + c * 16);
                float4* o1 = (float4*)(g_y + (size_t)n1 * 128 + half * 64 + c * 16);
#pragma unroll
                for (int q = 0; q < 4; q++) {
                    if (v0) o0[q] = make_float4(d[0 + 0][2 * q][0], 0.f, 0.f, 0.f);  // placeholder
                }
                // (rewritten below without placeholder)
#pragma unroll
                for (int q = 0; q < 4; q++) {
                    if (v0) o0[q] = make_float4(d[t][2 * q][0], d[t][2 * q][1],
                                                d[t][2 * q + 1][0], d[t][2 * q + 1][1]);
                    if (v1) o1[q] = make_float4(d[t][2 * q][2], d[t][2 * q][3],
                                                d[t][2 * q + 1][2], d[t][2 * q + 1][3]);
                }
            }
        }
        __syncwarp();
    }
}

// ================= EDGE KERNEL =================
#define E_SMEM 204032

__global__ void __launch_bounds__(256, 1) edge_kernel(
    float* eout,
    const int* __restrict__ src, const int* __restrict__ dst,
    const float* __restrict__ W0, const float* __restrict__ b0,
    const float* __restrict__ W1, const float* __restrict__ b1,
    const float* __restrict__ W2, const float* __restrict__ b2,
    const float* __restrict__ gam, const float* __restrict__ bet, int fin)
{
    extern __shared__ char sm[];
    const int tid = threadIdx.x, wid = tid >> 5, lane = tid & 31;
    const uint32_t smb = smem_u32(sm);

    stage_w_perm(sm + 147456, sm + 156672, W0 + 128 * 64, 144, tid, 256);  // e-part, K perm
    stage_w(sm + 165888, sm + 175104, W1, 64, 144, tid, 256);
    stage_w(sm + 184320, sm + 193536, W2, 64, 144, tid, 256);
    float* fb = (float*)(sm + 202752);
    if (tid < 64) {
        fb[tid] = b0[tid]; fb[64 + tid] = b1[tid]; fb[128 + tid] = b2[tid];
        fb[192 + tid] = gam[tid]; fb[256 + tid] = bet[tid];
    }
    __syncthreads();

    const uint32_t aHiB[2] = { smb + wid * 4608, smb + 36864 + wid * 4608 };
    const uint32_t aLoB[2] = { smb + 73728 + wid * 4608, smb + 110592 + wid * 4608 };

    const int tq = lane >> 3;
    const int rA = (lane & 7) + ((tq & 1) << 3);
    const int kA = (tq >> 1) << 3;
    const int ofsB144 = ((tq >> 1) * 8 + (lane & 7)) * 144 + (tq & 1) * 16;
    const uint32_t b1h = smb + 147456 + ofsB144, b1l = smb + 156672 + ofsB144;
    const uint32_t b2h = smb + 165888 + ofsB144, b2l = smb + 175104 + ofsB144;
    const uint32_t b3h = smb + 184320 + ofsB144, b3l = smb + 193536 + ofsB144;

    const int g = lane >> 2, c = lane & 3;
    const int grr = lane >> 3, gcc = lane & 7;

    const int NWT = NE / 32;
    const int stride = gridDim.x * 8;
    int wt = blockIdx.x * 8 + wid;
    int buf = 0;

    // prologue: gather tile 0 + its indices
    int sI[2][2], dI[2][2];
    if (wt < NWT) {
#pragma unroll
        for (int j = 0; j < 8; j++) {
            const int row = j * 4 + grr;
            const int ea = wt * 32 + row;
            cpasync16(aHiB[0] + row * 144 + gcc * 16,
                      (const char*)(g_ehi + (size_t)ea * 64) + gcc * 16);
            cpasync16(aLoB[0] + row * 144 + gcc * 16,
                      (const char*)(g_elo + (size_t)ea * 64) + gcc * 16);
        }
#pragma unroll
        for (int t = 0; t < 2; t++) {
            const int b = wt * 32 + 16 * t + g;
            sI[t][0] = __ldg(src + b); sI[t][1] = __ldg(src + b + 8);
            dI[t][0] = __ldg(dst + b); dI[t][1] = __ldg(dst + b + 8);
        }
    }
    CP_COMMIT();

    for (; wt < NWT; wt += stride) {
        const int wtn = wt + stride;
        if (wtn < NWT) {
#pragma unroll
            for (int j = 0; j < 8; j++) {
                const int row = j * 4 + grr;
                const int ean = wtn * 32 + row;
                cpasync16(aHiB[buf ^ 1] + row * 144 + gcc * 16,
                          (const char*)(g_ehi + (size_t)ean * 64) + gcc * 16);
                cpasync16(aLoB[buf ^ 1] + row * 144 + gcc * 16,
                          (const char*)(g_elo + (size_t)ean * 64) + gcc * 16);
            }
            CP_COMMIT();
        }

        // y-init: addresses ready (indices prefetched); vectorized LDG.128
        float d[2][8][4];
#pragma unroll
        for (int t = 0; t < 2; t++) {
            const float4* ys0 = (const float4*)(g_y + (size_t)sI[t][0] * 128 + c * 16);
            const float4* yd0 = (const float4*)(g_y + (size_t)dI[t][0] * 128 + 64 + c * 16);
            const float4* ys1 = (const float4*)(g_y + (size_t)sI[t][1] * 128 + c * 16);
            const float4* yd1 = (const float4*)(g_y + (size_t)dI[t][1] * 128 + 64 + c * 16);
#pragma unroll
            for (int q = 0; q < 4; q++) {
                float4 a = ys0[q], b = yd0[q];
                d[t][2 * q][0] = a.x + b.x;     d[t][2 * q][1] = a.y + b.y;
                d[t][2 * q + 1][0] = a.z + b.z; d[t][2 * q + 1][1] = a.w + b.w;
                a = ys1[q]; b = yd1[q];
                d[t][2 * q][2] = a.x + b.x;     d[t][2 * q][3] = a.y + b.y;
                d[t][2 * q + 1][2] = a.z + b.z; d[t][2 * q + 1][3] = a.w + b.w;
            }
        }

        // prefetch next tile's indices (consumed next iteration)
        int nsI[2][2], ndI[2][2];
        if (wtn < NWT) {
#pragma unroll
            for (int t = 0; t < 2; t++) {
                const int b = wtn * 32 + 16 * t + g;
                nsI[t][0] = __ldg(src + b); nsI[t][1] = __ldg(src + b + 8);
                ndI[t][0] = __ldg(dst + b); ndI[t][1] = __ldg(dst + b + 8);
            }
        }

        if (wtn < NWT) { CP_WAIT1(); } else { CP_WAIT0(); }
        __syncwarp();

        const uint32_t aHi[2] = { aHiB[buf] + rA * 144 + kA * 2,
                                  aHiB[buf] + (16 + rA) * 144 + kA * 2 };
        const uint32_t aLo[2] = { aLoB[buf] + rA * 144 + kA * 2,
                                  aLoB[buf] + (16 + rA) * 144 + kA * 2 };
        layer_smemA2<4>(d, aHi, aLo, b1h, b1l, 2304);

        uint32_t aH[2][4][4], aL[2][4][4];
        inter_reg2(d, fb, c, aH, aL);
        layer_regA2(d, aH, aL, b2h, b2l, 2304);
        inter_reg2(d, fb + 64, c, aH, aL);
        layer_regA2(d, aH, aL, b3h, b3l, 2304);

        char* aHiP = sm + (buf ? 36864 : 0) + wid * 4608;
        char* aLoP = sm + 73728 + (buf ? 36864 : 0) + wid * 4608;
        const float* b2v = fb + 128;
        const float* gmp = fb + 192;
        const float* btp = fb + 256;
#pragma unroll
        for (int t = 0; t < 2; t++) {
            const int r0 = 16 * t + g;
#pragma unroll
            for (int nt = 0; nt < 8; nt++) {
                int col = nt * 8 + 2 * c;
                float2 b = *(const float2*)(b2v + col);
                d[t][nt][0] += b.x; d[t][nt][1] += b.y;
                d[t][nt][2] += b.x; d[t][nt][3] += b.y;
            }
            float s0 = 0, q0 = 0, s1 = 0, q1 = 0;
#pragma unroll
            for (int nt = 0; nt < 8; nt++) {
                s0 += d[t][nt][0] + d[t][nt][1];
                q0 += d[t][nt][0] * d[t][nt][0] + d[t][nt][1] * d[t][nt][1];
                s1 += d[t][nt][2] + d[t][nt][3];
                q1 += d[t][nt][2] * d[t][nt][2] + d[t][nt][3] * d[t][nt][3];
            }
#pragma unroll
            for (int o = 1; o <= 2; o <<= 1) {
                s0 += __shfl_xor_sync(0xffffffffu, s0, o);
                q0 += __shfl_xor_sync(0xffffffffu, q0, o);
                s1 += __shfl_xor_sync(0xffffffffu, s1, o);
                q1 += __shfl_xor_sync(0xffffffffu, q1, o);
            }
            const float mu0 = s0 * (1.f / 64.f), mu1 = s1 * (1.f / 64.f);
            const float ri0 = rsqrtf(q0 * (1.f / 64.f) - mu0 * mu0 + EPS_LN);
            const float ri1 = rsqrtf(q1 * (1.f / 64.f) - mu1 * mu1 + EPS_LN);
            const int ea0 = wt * 32 + r0, ea1 = ea0 + 8;
            float* eo0 = eout + (size_t)ea0 * 64;
            float* eo1 = eout + (size_t)ea1 * 64;
            float* ag0 = g_agg + (size_t)dI[t][0] * 64 + c * 16;
            float* ag1 = g_agg + (size_t)dI[t][1] * 64 + c * 16;
#pragma unroll
            for (int ch = 0; ch < 2; ch++) {
                float a0v[8], a1v[8];
                uint32_t h0a[4], l0a[4], h1a[4], l1a[4];
#pragma unroll
                for (int k2 = 0; k2 < 4; k2++) {
                    const int nt = ch * 4 + k2;
                    const int col = nt * 8 + 2 * c;
                    const int so = (c * 8 + nt) * 4;   // fragment slot byte offset
                    float2 gmv = *(const float2*)(gmp + col);
                    float2 btv = *(const float2*)(btp + col);
                    float2 e0 = join2(*(const uint32_t*)(aHiP + r0 * 144 + so),
                                      *(const uint32_t*)(aLoP + r0 * 144 + so));
                    float2 e1 = join2(*(const uint32_t*)(aHiP + (r0 + 8) * 144 + so),
                                      *(const uint32_t*)(aLoP + (r0 + 8) * 144 + so));
                    float o0 = (d[t][nt][0] - mu0) * ri0 * gmv.x + btv.x + e0.x;
                    float o1 = (d[t][nt][1] - mu0) * ri0 * gmv.y + btv.y + e0.y;
                    float p0 = (d[t][nt][2] - mu1) * ri1 * gmv.x + btv.x + e1.x;
                    float p1 = (d[t][nt][3] - mu1) * ri1 * gmv.y + btv.y + e1.y;
                    a0v[k2 * 2] = o0; a0v[k2 * 2 + 1] = o1;
                    a1v[k2 * 2] = p0; a1v[k2 * 2 + 1] = p1;
                    if (fin) {
                        *(float2*)(eo0 + col) = make_float2(o0, o1);
                        *(float2*)(eo1 + col) = make_float2(p0, p1);
                    } else {
                        split2(o0, o1, h0a[k2], l0a[k2]);
                        split2(p0, p1, h1a[k2], l1a[k2]);
                    }
                }
                red4(ag0 + ch * 8,     a0v[0], a0v[1], a0v[2], a0v[3]);
                red4(ag0 + ch * 8 + 4, a0v[4], a0v[5], a0v[6], a0v[7]);
                red4(ag1 + ch * 8,     a1v[0], a1v[1], a1v[2], a1v[3]);
                red4(ag1 + ch * 8 + 4, a1v[4], a1v[5], a1v[6], a1v[7]);
                if (!fin) {
                    *(uint4*)((char*)g_ehi + (size_t)ea0 * 128 + c * 32 + ch * 16)
                        = make_uint4(h0a[0], h0a[1], h0a[2], h0a[3]);
                    *(uint4*)((char*)g_elo + (size_t)ea0 * 128 + c * 32 + ch * 16)
                        = make_uint4(l0a[0], l0a[1], l0a[2], l0a[3]);
                    *(uint4*)((char*)g_ehi + (size_t)ea1 * 128 + c * 32 + ch * 16)
                        = make_uint4(h1a[0], h1a[1], h1a[2], h1a[3]);
                    *(uint4*)((char*)g_elo + (size_t)ea1 * 128 + c * 32 + ch * 16)
                        = make_uint4(l1a[0], l1a[1], l1a[2], l1a[3]);
                }
            }
        }
#pragma unroll
        for (int t = 0; t < 2; t++) {
            sI[t][0] = nsI[t][0]; sI[t][1] = nsI[t][1];
            dI[t][0] = ndI[t][0]; dI[t][1] = ndI[t][1];
        }
        buf ^= 1;
    }
}

// ================= NODE KERNEL =================
#define N_SMEM 212224

__global__ void __launch_bounds__(256, 1) node_kernel(
    float* xout,
    const float* __restrict__ W0, const float* __restrict__ b0,
    const float* __restrict__ W1, const float* __restrict__ b1,
    const float* __restrict__ W2, const float* __restrict__ b2,
    const float* __restrict__ gam, const float* __restrict__ bet, int fin)
{
    extern __shared__ char sm[];
    const int tid = threadIdx.x, wid = tid >> 5, lane = tid & 31;
    const uint32_t smb = smem_u32(sm);

    // node B1: K=128 over [x | agg], BOTH halves fragment-major -> permute each half
    for (int idx = tid; idx < 128 * 64; idx += 256) {
        int kpos = idx >> 6, n = idx & 63;
        int base = (kpos >= 64) ? 64 : 0;
        float f = W0[(base + kperm(kpos & 63)) * 64 + n];
        __nv_bfloat16 h = __float2bfloat16_rn(f);
        __nv_bfloat16 l = __float2bfloat16_rn(f - __bfloat162float(h));
        int off = n * 272 + kpos * 2;
        *(__nv_bfloat16*)(sm + 139264 + off) = h;
        *(__nv_bfloat16*)(sm + 156672 + off) = l;
    }
    stage_w(sm + 174080, sm + 183296, W1, 64, 144, tid, 256);
    stage_w(sm + 192512, sm + 201728, W2, 64, 144, tid, 256);
    float* fb = (float*)(sm + 210944);
    if (tid < 64) {
        fb[tid] = b0[tid]; fb[64 + tid] = b1[tid]; fb[128 + tid] = b2[tid];
        fb[192 + tid] = gam[tid]; fb[256 + tid] = bet[tid];
    }
    __syncthreads();

    char* aHiP = sm + wid * 8704;
    char* aLoP = sm + 69632 + wid * 8704;
    const uint32_t aHiB = smb + wid * 8704, aLoB = smb + 69632 + wid * 8704;

    const int tq = lane >> 3;
    const int rA = (lane & 7) + ((tq & 1) << 3);
    const int kA = (tq >> 1) << 3;
    const uint32_t aHi[2] = { aHiB + rA * 272 + kA * 2, aHiB + (16 + rA) * 272 + kA * 2 };
    const uint32_t aLo[2] = { aLoB + rA * 272 + kA * 2, aLoB + (16 + rA) * 272 + kA * 2 };
    const int ofsB272 = ((tq >> 1) * 8 + (lane & 7)) * 272 + (tq & 1) * 16;
    const int ofsB144 = ((tq >> 1) * 8 + (lane & 7)) * 144 + (tq & 1) * 16;
    const uint32_t b1h = smb + 139264 + ofsB272, b1l = smb + 156672 + ofsB272;
    const uint32_t b2h = smb + 174080 + ofsB144, b2l = smb + 183296 + ofsB144;
    const uint32_t b3h = smb + 192512 + ofsB144, b3l = smb + 201728 + ofsB144;

    const int g = lane >> 2, c = lane & 3;
    const int grr = lane >> 3, gcc = lane & 7;
    const int arr = lane >> 4, acc_ = lane & 15;

    const int NWT = (NN + 31) / 32;
    for (int wt = blockIdx.x * 8 + wid; wt < NWT; wt += gridDim.x * 8) {
#pragma unroll
        for (int j = 0; j < 8; j++) {
            const int row = j * 4 + grr;
            const int n = wt * 32 + row;
            const int nc = (n < NN) ? n : (NN - 1);
            *(uint4*)(aHiP + row * 272 + gcc * 16) =
                *(const uint4*)((const char*)(g_xhi + (size_t)nc * 64) + gcc * 16);
            *(uint4*)(aLoP + row * 272 + gcc * 16) =
                *(const uint4*)((const char*)(g_xlo + (size_t)nc * 64) + gcc * 16);
        }
#pragma unroll
        for (int j = 0; j < 16; j++) {
            const int row = j * 2 + arr;
            const int n = wt * 32 + row;
            const int nc = (n < NN) ? n : (NN - 1);
            float4 v = *(const float4*)(g_agg + (size_t)nc * 64 + acc_ * 4);
            uint32_t h0, l0, h1, l1;
            split2(v.x, v.y, h0, l0);
            split2(v.z, v.w, h1, l1);
            *(uint2*)(aHiP + row * 272 + 128 + acc_ * 8) = make_uint2(h0, h1);
            *(uint2*)(aLoP + row * 272 + 128 + acc_ * 8) = make_uint2(l0, l1);
        }
        __syncwarp();

        float d[2][8][4];
#pragma unroll
        for (int t = 0; t < 2; t++)
#pragma unroll
            for (int nt = 0; nt < 8; nt++)
                d[t][nt][0] = d[t][nt][1] = d[t][nt][2] = d[t][nt][3] = 0.f;
        layer_smemA2<8>(d, aHi, aLo, b1h, b1l, 4352);
        uint32_t aH[2][4][4], aL[2][4][4];
        inter_reg2(d, fb, c, aH, aL);
        layer_regA2(d, aH, aL, b2h, b2l, 2304);
        inter_reg2(d, fb + 64, c, aH, aL);
        layer_regA2(d, aH, aL, b3h, b3l, 2304);

        const float* b2v = fb + 128;
        const float* gmp = fb + 192;
        const float* btp = fb + 256;
#pragma unroll
        for (int t = 0; t < 2; t++) {
            const int r0 = 16 * t + g;
#pragma unroll
            for (int nt = 0; nt < 8; nt++) {
                int col = nt * 8 + 2 * c;
                float2 b = *(const float2*)(b2v + col);
                d[t][nt][0] += b.x; d[t][nt][1] += b.y;
                d[t][nt][2] += b.x; d[t][nt][3] += b.y;
            }
            float s0 = 0, q0 = 0, s1 = 0, q1 = 0;
#pragma unroll
            for (int nt = 0; nt < 8; nt++) {
                s0 += d[t][nt][0] + d[t][nt][1];
                q0 += d[t][nt][0] * d[t][nt][0] + d[t][nt][1] * d[t][nt][1];
                s1 += d[t][nt][2] + d[t][nt][3];
                q1 += d[t][nt][2] * d[t][nt][2] + d[t][nt][3] * d[t][nt][3];
            }
#pragma unroll
            for (int o = 1; o <= 2; o <<= 1) {
                s0 += __shfl_xor_sync(0xffffffffu, s0, o);
                q0 += __shfl_xor_sync(0xffffffffu, q0, o);
                s1 += __shfl_xor_sync(0xffffffffu, s1, o);
                q1 += __shfl_xor_sync(0xffffffffu, q1, o);
            }
            const float mu0 = s0 * (1.f / 64.f), mu1 = s1 * (1.f / 64.f);
            const float ri0 = rsqrtf(q0 * (1.f / 64.f) - mu0 * mu0 + EPS_LN);
            const float ri1 = rsqrtf(q1 * (1.f / 64.f) - mu1 * mu1 + EPS_LN);
            const int n0 = wt * 32 + r0, n1 = n0 + 8;
            const bool v0 = n0 < NN, v1 = n1 < NN;
            float* xo0 = xout + (size_t)n0 * 64;
            float* xo1 = xout + (size_t)n1 * 64;
#pragma unroll
            for (int ch = 0; ch < 2; ch++) {
                uint32_t h0a[4], l0a[4], h1a[4], l1a[4];
#pragma unroll
                for (int k2 = 0; k2 < 4; k2++) {
                    const int nt = ch * 4 + k2;
                    const int col = nt * 8 + 2 * c;
                    const int so = (c * 8 + nt) * 4;
                    float2 gmv = *(const float2*)(gmp + col);
                    float2 btv = *(const float2*)(btp + col);
                    float2 x0 = join2(*(const uint32_t*)(aHiP + r0 * 272 + so),
                                      *(const uint32_t*)(aLoP + r0 * 272 + so));
                    float2 x1 = join2(*(const uint32_t*)(aHiP + (r0 + 8) * 272 + so),
                                      *(const uint32_t*)(aLoP + (r0 + 8) * 272 + so));
                    float o0 = (d[t][nt][0] - mu0) * ri0 * gmv.x + btv.x + x0.x;
                    float o1 = (d[t][nt][1] - mu0) * ri0 * gmv.y + btv.y + x0.y;
                    float p0 = (d[t][nt][2] - mu1) * ri1 * gmv.x + btv.x + x1.x;
                    float p1 = (d[t][nt][3] - mu1) * ri1 * gmv.y + btv.y + x1.y;
                    if (fin) {
                        if (v0) *(float2*)(xo0 + col) = make_float2(o0, o1);
                        if (v1) *(float2*)(xo1 + col) = make_float2(p0, p1);
                    } else {
                        split2(o0, o1, h0a[k2], l0a[k2]);
                        split2(p0, p1, h1a[k2], l1a[k2]);
                    }
                }
                if (!fin) {
                    if (v0) {
                        *(uint4*)((char*)g_xhi + (size_t)n0 * 128 + c * 32 + ch * 16)
                            = make_uint4(h0a[0], h0a[1], h0a[2], h0a[3]);
                        *(uint4*)((char*)g_xlo + (size_t)n0 * 128 + c * 32 + ch * 16)
                            = make_uint4(l0a[0], l0a[1], l0a[2], l0a[3]);
                    }
                    if (v1) {
                        *(uint4*)((char*)g_xhi + (size_t)n1 * 128 + c * 32 + ch * 16)
                            = make_uint4(h1a[0], h1a[1], h1a[2], h1a[3]);
                        *(uint4*)((char*)g_xlo + (size_t)n1 * 128 + c * 32 + ch * 16)
                            = make_uint4(l1a[0], l1a[1], l1a[2], l1a[3]);
                    }
                }
            }
        }
        __syncwarp();
    }
}

// ================= streaming split (fragment-major output) =================
__global__ void split_perm_kernel(const float* __restrict__ in,
                                  __nv_bfloat16* __restrict__ hi,
                                  __nv_bfloat16* __restrict__ lo, int nrows) {
    const int gw = (blockIdx.x * blockDim.x + threadIdx.x) >> 5;
    const int lane = threadIdx.x & 31;
    const int jq = (lane & 7) * 8 + (lane >> 3) * 2;   // logical col pair for slot=lane
    const int nwarps = gridDim.x * (blockDim.x >> 5);
    for (int row = gw; row < nrows; row += nwarps) {
        float2 v = *(const float2*)(in + (size_t)row * 64 + jq);
        uint32_t h, l;
        split2(v.x, v.y, h, l);
        ((uint32_t*)(hi + (size_t)row * 64))[lane] = h;
        ((uint32_t*)(lo + (size_t)row * 64))[lane] = l;
    }
}

// ================= launcher =================
extern "C" void kernel_launch(void* const* d_in, const int* in_sizes, int n_in,
                              void* d_out, int out_size) {
    const float* x_in = (const float*)d_in[0];
    const float* e_in = (const float*)d_in[1];
    const int* ei = (const int*)d_in[2];
    const int *src = ei, *dst = ei + NE;
    const float* ew0 = (const float*)d_in[3];  const float* eb0 = (const float*)d_in[4];
    const float* ew1 = (const float*)d_in[5];  const float* eb1 = (const float*)d_in[6];
    const float* ew2 = (const float*)d_in[7];  const float* eb2 = (const float*)d_in[8];
    const float* eg  = (const float*)d_in[9];  const float* ebt = (const float*)d_in[10];
    const float* nw0 = (const float*)d_in[11]; const float* nb0 = (const float*)d_in[12];
    const float* nw1 = (const float*)d_in[13]; const float* nb1 = (const float*)d_in[14];
    const float* nw2 = (const float*)d_in[15]; const float* nb2 = (const float*)d_in[16];
    const float* ng  = (const float*)d_in[17]; const float* nbt = (const float*)d_in[18];

    float* out_x = (float*)d_out;
    float* out_e = (float*)d_out + (size_t)NN * 64;

    __nv_bfloat16 *xhi, *xlo, *ehi, *elo;
    cudaGetSymbolAddress((void**)&xhi, g_xhi);
    cudaGetSymbolAddress((void**)&xlo, g_xlo);
    cudaGetSymbolAddress((void**)&ehi, g_ehi);
    cudaGetSymbolAddress((void**)&elo, g_elo);

    cudaFuncSetAttribute(edge_kernel, cudaFuncAttributeMaxDynamicSharedMemorySize, E_SMEM);
    cudaFuncSetAttribute(node_kernel, cudaFuncAttributeMaxDynamicSharedMemorySize, N_SMEM);
    cudaFuncSetAttribute(node_pre_kernel, cudaFuncAttributeMaxDynamicSharedMemorySize, PRE_SMEM);

    // keep edge_kernel at launch index 3 (ncu capture slot)
    split_perm_kernel<<<512, 256>>>(x_in, xhi, xlo, NN);            // 0
    split_perm_kernel<<<1024, 256>>>(e_in, ehi, elo, NE);           // 1

    const int EW0S = 192 * 64, EWS = 64 * 64, NW0S = 128 * 64;
    for (int i = 0; i < 3; i++) {
        const int fin = (i == 2) ? 1 : 0;
        node_pre_kernel<<<148, 256, PRE_SMEM>>>(ew0 + i * EW0S);    // 2, 5, 8
        edge_kernel<<<148, 256, E_SMEM>>>(                           // 3, 6, 9
            out_e, src, dst,
            ew0 + i * EW0S, eb0 + i * 64, ew1 + i * EWS, eb1 + i * 64,
            ew2 + i * EWS, eb2 + i * 64, eg + i * 64, ebt + i * 64, fin);
        node_kernel<<<148, 256, N_SMEM>>>(                           // 4, 7, 10
            out_x,
            nw0 + i * NW0S, nb0 + i * 64, nw1 + i * EWS, nb1 + i * 64,
            nw2 + i * EWS, nb2 + i * 64, ng + i * 64, nbt + i * 64, fin);
    }
}